// round 6
// baseline (speedup 1.0000x reference)
#include <cuda_runtime.h>
#include <cuda_bf16.h>
#include <cstdint>

#define N_NODES 200000
#define N_EDGES 6400000
#define N_LAYERS 3

// Scratch (no cudaMalloc allowed)
__device__ float4 g_T[N_NODES];    // (t0, t1, t2, deg) accumulators
__device__ float  g_A[N_NODES];    // current per-node cumulative scalar
__device__ float  g_q1[N_NODES];   // M @ A_1
__device__ float  g_q2[N_NODES];   // M @ A_2
// per-layer 16 floats: [0..11]=W row, [12]=b, [13]=sA=sum(w[0:4]), [14]=sB=sum(w[4:8])
__device__ float  g_wc[N_LAYERS * 16];

// ---------------------------------------------------------------------------
// 1. init: zero scratch; block 0 also computes per-layer weight constants
// ---------------------------------------------------------------------------
__global__ void init_kernel(const float* __restrict__ W,
                            const float* __restrict__ b,
                            float4* __restrict__ T,
                            float* __restrict__ q1,
                            float* __restrict__ q2) {
    int n = blockIdx.x * blockDim.x + threadIdx.x;
    if (blockIdx.x == 0 && threadIdx.x < N_LAYERS) {
        int i = threadIdx.x;
        float sA = 0.f, sB = 0.f;
        #pragma unroll
        for (int j = 0; j < 12; j++) {
            float w = W[i * 12 + j];
            g_wc[i * 16 + j] = w;
            if (j < 4)       sA += w;
            else if (j < 8)  sB += w;
        }
        g_wc[i * 16 + 12] = b[i];
        g_wc[i * 16 + 13] = sA;
        g_wc[i * 16 + 14] = sB;
    }
    if (n < N_NODES) {
        T[n] = make_float4(0.f, 0.f, 0.f, 0.f);
        q1[n] = 0.f;
        q2[n] = 0.f;
    }
}

// ---------------------------------------------------------------------------
__device__ __forceinline__ void red_add_v4(float4* ptr, float a, float b,
                                           float c, float d) {
    asm volatile("red.global.add.v4.f32 [%0], {%1, %2, %3, %4};"
                 :: "l"(__cvta_generic_to_global(ptr)),
                    "f"(a), "f"(b), "f"(c), "f"(d)
                 : "memory");
}

// ---------------------------------------------------------------------------
// 2. ONE heavy edge pass for all 3 layers, 8 edges per thread:
//    T[dst] += ( ws_l.z0[src] + w_geo_l.(r,rhat)  for l=0..2 , 1 )
// ---------------------------------------------------------------------------
__global__ void __launch_bounds__(256)
heavy_edge_kernel(const int4* __restrict__ src4,
                  const int4* __restrict__ dst4,
                  const float4* __restrict__ r4,
                  const float4* __restrict__ rhat4,
                  const float4* __restrict__ z0,
                  float4* __restrict__ T) {
    int t = blockIdx.x * blockDim.x + threadIdx.x;
    if (t >= N_EDGES / 8) return;

    int4   s0 = __ldcs(src4 + 2 * t);
    int4   s1 = __ldcs(src4 + 2 * t + 1);
    int4   d0 = __ldcs(dst4 + 2 * t);
    int4   d1 = __ldcs(dst4 + 2 * t + 1);
    float4 r0 = __ldcs(r4 + 2 * t);
    float4 r1 = __ldcs(r4 + 2 * t + 1);
    float4 h[6];
    #pragma unroll
    for (int i = 0; i < 6; i++) h[i] = __ldcs(rhat4 + 6 * t + i);

    int ss[8] = {s0.x, s0.y, s0.z, s0.w, s1.x, s1.y, s1.z, s1.w};
    int dd[8] = {d0.x, d0.y, d0.z, d0.w, d1.x, d1.y, d1.z, d1.w};
    float rr[8] = {r0.x, r0.y, r0.z, r0.w, r1.x, r1.y, r1.z, r1.w};
    const float* hf = (const float*)h;   // 24 rhat floats

    // 8 independent random gathers — maximize MLP before any RED
    float4 zs[8];
    #pragma unroll
    for (int e = 0; e < 8; e++) zs[e] = __ldg(&z0[ss[e]]);

    float tv[8][3];
    #pragma unroll
    for (int l = 0; l < N_LAYERS; l++) {
        const float* wc = g_wc + l * 16;
        float w0 = wc[0], w1 = wc[1], w2 = wc[2], w3 = wc[3];
        float w8 = wc[8], w9 = wc[9], wa = wc[10], wb = wc[11];
        #pragma unroll
        for (int e = 0; e < 8; e++) {
            tv[e][l] = w0 * zs[e].x + w1 * zs[e].y + w2 * zs[e].z + w3 * zs[e].w
                     + w8 * rr[e]
                     + w9 * hf[3 * e] + wa * hf[3 * e + 1] + wb * hf[3 * e + 2];
        }
    }

    #pragma unroll
    for (int e = 0; e < 8; e++)
        red_add_v4(&T[dd[e]], tv[e][0], tv[e][1], tv[e][2], 1.f);
}

// ---------------------------------------------------------------------------
// 3. Light edge pass, 8 edges per thread: q[dst] += A[src]
// ---------------------------------------------------------------------------
__global__ void __launch_bounds__(256)
light_edge_kernel(const int4* __restrict__ src4,
                  const int4* __restrict__ dst4,
                  const float* __restrict__ A,
                  float* __restrict__ q) {
    int t = blockIdx.x * blockDim.x + threadIdx.x;
    if (t >= N_EDGES / 8) return;

    int4 s0 = __ldcs(src4 + 2 * t);
    int4 s1 = __ldcs(src4 + 2 * t + 1);
    int4 d0 = __ldcs(dst4 + 2 * t);
    int4 d1 = __ldcs(dst4 + 2 * t + 1);

    int ss[8] = {s0.x, s0.y, s0.z, s0.w, s1.x, s1.y, s1.z, s1.w};
    int dd[8] = {d0.x, d0.y, d0.z, d0.w, d1.x, d1.y, d1.z, d1.w};

    float av[8];
    #pragma unroll
    for (int e = 0; e < 8; e++) av[e] = __ldg(&A[ss[e]]);

    #pragma unroll
    for (int e = 0; e < 8; e++) atomicAdd(&q[dd[e]], av[e]);
}

// ---------------------------------------------------------------------------
// 4. Node update layer 0 (2 nodes/thread): A1 = t0 + deg*(b0 + wd0.z0)
//    Also writes the x-half of the output (out_x = z0).
// ---------------------------------------------------------------------------
__global__ void node0_kernel(const float4* __restrict__ z0,
                             const float4* __restrict__ T,
                             float* __restrict__ A,
                             float4* __restrict__ out) {
    int base = 2 * (blockIdx.x * blockDim.x + threadIdx.x);
    const float* wc = g_wc;  // layer 0
    #pragma unroll
    for (int k = 0; k < 2; k++) {
        int n = base + k;
        if (n >= N_NODES) return;
        float4 z = z0[n];
        float4 tt = T[n];
        float pd = wc[12] + wc[4]*z.x + wc[5]*z.y + wc[6]*z.z + wc[7]*z.w;
        A[n] = tt.x + tt.w * pd;
        out[N_NODES + n] = z;     // x output
    }
}

// ---------------------------------------------------------------------------
// 5. Node update layer 1: A2 = A1 + t1 + sA1*q1 + deg*(b1 + wd1.z0 + sB1*A1)
// ---------------------------------------------------------------------------
__global__ void node_update1_kernel(const float4* __restrict__ z0,
                                    const float4* __restrict__ T,
                                    const float* __restrict__ q,
                                    float* __restrict__ A) {
    int base = 2 * (blockIdx.x * blockDim.x + threadIdx.x);
    const float* wc = g_wc + 16;  // layer 1
    #pragma unroll
    for (int k = 0; k < 2; k++) {
        int n = base + k;
        if (n >= N_NODES) return;
        float4 z = z0[n];
        float4 tt = T[n];
        float  a = A[n];
        float pd = wc[12] + wc[4]*z.x + wc[5]*z.y + wc[6]*z.z + wc[7]*z.w + wc[14]*a;
        A[n] = a + tt.y + wc[13] * q[n] + tt.w * pd;
    }
}

// ---------------------------------------------------------------------------
// 6. Node update layer 2 + finalize:
//    A3 = A2 + t2 + sA2*q2 + deg*(b2 + wd2.z0 + sB2*A2);  out_z = z0 + A3
// ---------------------------------------------------------------------------
__global__ void node_update2_final_kernel(const float4* __restrict__ z0,
                                          const float4* __restrict__ T,
                                          const float* __restrict__ q,
                                          const float* __restrict__ A,
                                          float4* __restrict__ out) {
    int base = 2 * (blockIdx.x * blockDim.x + threadIdx.x);
    const float* wc = g_wc + 32;  // layer 2
    #pragma unroll
    for (int k = 0; k < 2; k++) {
        int n = base + k;
        if (n >= N_NODES) return;
        float4 z = z0[n];
        float4 tt = T[n];
        float  a = A[n];
        float pd = wc[12] + wc[4]*z.x + wc[5]*z.y + wc[6]*z.z + wc[7]*z.w + wc[14]*a;
        float a3 = a + tt.z + wc[13] * q[n] + tt.w * pd;
        out[n] = make_float4(z.x + a3, z.y + a3, z.z + a3, z.w + a3);
    }
}

// ---------------------------------------------------------------------------
extern "C" void kernel_launch(void* const* d_in, const int* in_sizes, int n_in,
                              void* d_out, int out_size) {
    const float* z    = (const float*)d_in[0];
    const float* r    = (const float*)d_in[1];
    const float* rhat = (const float*)d_in[2];
    const float* W    = (const float*)d_in[3];
    const float* b    = (const float*)d_in[4];
    const int*   src  = (const int*)d_in[5];
    const int*   dst  = (const int*)d_in[6];
    float* out = (float*)d_out;

    float4 *T; float *A, *q1, *q2;
    cudaGetSymbolAddress((void**)&T,  g_T);
    cudaGetSymbolAddress((void**)&A,  g_A);
    cudaGetSymbolAddress((void**)&q1, g_q1);
    cudaGetSymbolAddress((void**)&q2, g_q2);

    const int NODE_BLOCKS  = (N_NODES + 255) / 256;
    const int NODE_BLOCKS2 = (N_NODES / 2 + 255) / 256;
    const int EDGE_BLOCKS8 = (N_EDGES / 8 + 255) / 256;

    init_kernel<<<NODE_BLOCKS, 256>>>(W, b, T, q1, q2);

    heavy_edge_kernel<<<EDGE_BLOCKS8, 256>>>((const int4*)src, (const int4*)dst,
                                             (const float4*)r, (const float4*)rhat,
                                             (const float4*)z, T);

    node0_kernel<<<NODE_BLOCKS2, 256>>>((const float4*)z, T, A, (float4*)out);

    light_edge_kernel<<<EDGE_BLOCKS8, 256>>>((const int4*)src, (const int4*)dst, A, q1);
    node_update1_kernel<<<NODE_BLOCKS2, 256>>>((const float4*)z, T, q1, A);

    light_edge_kernel<<<EDGE_BLOCKS8, 256>>>((const int4*)src, (const int4*)dst, A, q2);
    node_update2_final_kernel<<<NODE_BLOCKS2, 256>>>((const float4*)z, T, q2, A,
                                                     (float4*)out);
}

// round 7
// speedup vs baseline: 1.0613x; 1.0613x over previous
#include <cuda_runtime.h>
#include <cuda_bf16.h>
#include <cstdint>

#define N_NODES 200000
#define N_EDGES 6400000
#define N_LAYERS 3

// Scratch (no cudaMalloc allowed)
__device__ float4 g_T[N_NODES];    // (t0, t1, t2, deg) accumulators
__device__ float  g_A[N_NODES];    // current per-node cumulative scalar
__device__ float  g_q1[N_NODES];   // M @ A_1
__device__ float  g_q2[N_NODES];   // M @ A_2
// per-layer 16 floats: [0..11]=W row, [12]=b, [13]=sA=sum(w[0:4]), [14]=sB=sum(w[4:8])
__device__ float  g_wc[N_LAYERS * 16];

// PDL: wait until the stream-predecessor kernel has completed (implicit
// trigger at predecessor completion since we never trigger early).
__device__ __forceinline__ void pdl_wait() {
    asm volatile("griddepcontrol.wait;" ::: "memory");
}

// ---------------------------------------------------------------------------
// 1. init: zero T; block 0 also computes per-layer weight constants
// ---------------------------------------------------------------------------
__global__ void init_kernel(const float* __restrict__ W,
                            const float* __restrict__ b,
                            float4* __restrict__ T) {
    int n = blockIdx.x * blockDim.x + threadIdx.x;
    if (blockIdx.x == 0 && threadIdx.x < N_LAYERS) {
        int i = threadIdx.x;
        float sA = 0.f, sB = 0.f;
        #pragma unroll
        for (int j = 0; j < 12; j++) {
            float w = W[i * 12 + j];
            g_wc[i * 16 + j] = w;
            if (j < 4)       sA += w;
            else if (j < 8)  sB += w;
        }
        g_wc[i * 16 + 12] = b[i];
        g_wc[i * 16 + 13] = sA;
        g_wc[i * 16 + 14] = sB;
    }
    if (n < N_NODES)
        T[n] = make_float4(0.f, 0.f, 0.f, 0.f);
}

// ---------------------------------------------------------------------------
__device__ __forceinline__ void red_add_v4(float4* ptr, float a, float b,
                                           float c, float d) {
    asm volatile("red.global.add.v4.f32 [%0], {%1, %2, %3, %4};"
                 :: "l"(__cvta_generic_to_global(ptr)),
                    "f"(a), "f"(b), "f"(c), "f"(d)
                 : "memory");
}

// ---------------------------------------------------------------------------
// 2. ONE heavy edge pass for all 3 layers, 4 edges per thread:
//    T[dst] += ( ws_l.z0[src] + w_geo_l.(r,rhat)  for l=0..2 , 1 )
// ---------------------------------------------------------------------------
__global__ void __launch_bounds__(256)
heavy_edge_kernel(const int4* __restrict__ src4,
                  const int4* __restrict__ dst4,
                  const float4* __restrict__ r4,
                  const float4* __restrict__ rhat4,
                  const float4* __restrict__ z0,
                  float4* __restrict__ T) {
    pdl_wait();
    int t = blockIdx.x * blockDim.x + threadIdx.x;
    if (t >= N_EDGES / 4) return;

    int4   s  = __ldcs(src4 + t);
    int4   d  = __ldcs(dst4 + t);
    float4 r  = __ldcs(r4   + t);
    float4 h0 = __ldcs(rhat4 + 3 * t + 0);
    float4 h1 = __ldcs(rhat4 + 3 * t + 1);
    float4 h2 = __ldcs(rhat4 + 3 * t + 2);

    float4 zs0 = __ldg(&z0[s.x]);
    float4 zs1 = __ldg(&z0[s.y]);
    float4 zs2 = __ldg(&z0[s.z]);
    float4 zs3 = __ldg(&z0[s.w]);

    float rr[4]    = {r.x, r.y, r.z, r.w};
    float rh[4][3] = {{h0.x, h0.y, h0.z}, {h0.w, h1.x, h1.y},
                      {h1.z, h1.w, h2.x}, {h2.y, h2.z, h2.w}};
    float4 zs[4]   = {zs0, zs1, zs2, zs3};
    int    dd[4]   = {d.x, d.y, d.z, d.w};

    float tv[4][3];
    #pragma unroll
    for (int l = 0; l < N_LAYERS; l++) {
        const float* wc = g_wc + l * 16;
        float w0 = wc[0], w1 = wc[1], w2 = wc[2], w3 = wc[3];
        float w8 = wc[8], w9 = wc[9], wa = wc[10], wb = wc[11];
        #pragma unroll
        for (int e = 0; e < 4; e++) {
            tv[e][l] = w0 * zs[e].x + w1 * zs[e].y + w2 * zs[e].z + w3 * zs[e].w
                     + w8 * rr[e] + w9 * rh[e][0] + wa * rh[e][1] + wb * rh[e][2];
        }
    }

    #pragma unroll
    for (int e = 0; e < 4; e++)
        red_add_v4(&T[dd[e]], tv[e][0], tv[e][1], tv[e][2], 1.f);
}

// ---------------------------------------------------------------------------
// 3. Light edge pass, 4 edges per thread: q[dst] += A[src]
// ---------------------------------------------------------------------------
__global__ void __launch_bounds__(256)
light_edge_kernel(const int4* __restrict__ src4,
                  const int4* __restrict__ dst4,
                  const float* __restrict__ A,
                  float* __restrict__ q) {
    pdl_wait();
    int t = blockIdx.x * blockDim.x + threadIdx.x;
    if (t >= N_EDGES / 4) return;

    int4 s = __ldcs(src4 + t);
    int4 d = __ldcs(dst4 + t);

    float a0 = __ldg(&A[s.x]);
    float a1 = __ldg(&A[s.y]);
    float a2 = __ldg(&A[s.z]);
    float a3 = __ldg(&A[s.w]);

    atomicAdd(&q[d.x], a0);
    atomicAdd(&q[d.y], a1);
    atomicAdd(&q[d.z], a2);
    atomicAdd(&q[d.w], a3);
}

// ---------------------------------------------------------------------------
// 4. Node update layer 0: A1 = t0 + deg*(b0 + wd0.z0)   (A0 = 0, q0 = 0)
//    Also zeroes q1 (consumed by the next light pass) and writes out_x = z0.
// ---------------------------------------------------------------------------
__global__ void node0_kernel(const float4* __restrict__ z0,
                             const float4* __restrict__ T,
                             float* __restrict__ A,
                             float* __restrict__ q1,
                             float4* __restrict__ out) {
    pdl_wait();
    int n = blockIdx.x * blockDim.x + threadIdx.x;
    if (n >= N_NODES) return;
    const float* wc = g_wc;  // layer 0
    float4 z = z0[n];
    float4 tt = T[n];
    float pd = wc[12] + wc[4]*z.x + wc[5]*z.y + wc[6]*z.z + wc[7]*z.w;
    A[n] = tt.x + tt.w * pd;
    q1[n] = 0.f;
    out[N_NODES + n] = z;     // x output
}

// ---------------------------------------------------------------------------
// 5. Node update layer 1: A2 = A1 + t1 + sA1*q1 + deg*(b1 + wd1.z0 + sB1*A1)
//    Also zeroes q2 (consumed by the next light pass).
// ---------------------------------------------------------------------------
__global__ void node_update1_kernel(const float4* __restrict__ z0,
                                    const float4* __restrict__ T,
                                    const float* __restrict__ q,
                                    float* __restrict__ A,
                                    float* __restrict__ q2) {
    pdl_wait();
    int n = blockIdx.x * blockDim.x + threadIdx.x;
    if (n >= N_NODES) return;
    const float* wc = g_wc + 16;  // layer 1
    float4 z = z0[n];
    float4 tt = T[n];
    float  a = A[n];
    float pd = wc[12] + wc[4]*z.x + wc[5]*z.y + wc[6]*z.z + wc[7]*z.w + wc[14]*a;
    A[n] = a + tt.y + wc[13] * q[n] + tt.w * pd;
    q2[n] = 0.f;
}

// ---------------------------------------------------------------------------
// 6. Node update layer 2 + finalize:
//    A3 = A2 + t2 + sA2*q2 + deg*(b2 + wd2.z0 + sB2*A2);  out_z = z0 + A3
// ---------------------------------------------------------------------------
__global__ void node_update2_final_kernel(const float4* __restrict__ z0,
                                          const float4* __restrict__ T,
                                          const float* __restrict__ q,
                                          const float* __restrict__ A,
                                          float4* __restrict__ out) {
    pdl_wait();
    int n = blockIdx.x * blockDim.x + threadIdx.x;
    if (n >= N_NODES) return;
    const float* wc = g_wc + 32;  // layer 2
    float4 z = z0[n];
    float4 tt = T[n];
    float  a = A[n];
    float pd = wc[12] + wc[4]*z.x + wc[5]*z.y + wc[6]*z.z + wc[7]*z.w + wc[14]*a;
    float a3 = a + tt.z + wc[13] * q[n] + tt.w * pd;
    out[n] = make_float4(z.x + a3, z.y + a3, z.z + a3, z.w + a3);
}

// ---------------------------------------------------------------------------
// PDL launch helper: programmatic stream serialization = overlap this
// kernel's launch/ramp with the predecessor's tail; griddepcontrol.wait at
// kernel entry preserves full completion ordering.
// ---------------------------------------------------------------------------
template <typename... Args>
static void launch_pdl(void (*kern)(Args...), dim3 grid, dim3 block,
                       Args... args) {
    cudaLaunchAttribute attr[1];
    attr[0].id = cudaLaunchAttributeProgrammaticStreamSerialization;
    attr[0].val.programmaticStreamSerializationAllowed = 1;
    cudaLaunchConfig_t cfg = {};
    cfg.gridDim = grid;
    cfg.blockDim = block;
    cfg.dynamicSmemBytes = 0;
    cfg.stream = 0;
    cfg.attrs = attr;
    cfg.numAttrs = 1;
    cudaLaunchKernelEx(&cfg, kern, args...);
}

// ---------------------------------------------------------------------------
extern "C" void kernel_launch(void* const* d_in, const int* in_sizes, int n_in,
                              void* d_out, int out_size) {
    const float* z    = (const float*)d_in[0];
    const float* r    = (const float*)d_in[1];
    const float* rhat = (const float*)d_in[2];
    const float* W    = (const float*)d_in[3];
    const float* b    = (const float*)d_in[4];
    const int*   src  = (const int*)d_in[5];
    const int*   dst  = (const int*)d_in[6];
    float* out = (float*)d_out;

    float4 *T; float *A, *q1, *q2;
    cudaGetSymbolAddress((void**)&T,  g_T);
    cudaGetSymbolAddress((void**)&A,  g_A);
    cudaGetSymbolAddress((void**)&q1, g_q1);
    cudaGetSymbolAddress((void**)&q2, g_q2);

    const dim3 blk(256);
    const dim3 NODE_GRID((N_NODES + 255) / 256);
    const dim3 EDGE_GRID((N_EDGES / 4 + 255) / 256);

    init_kernel<<<NODE_GRID, blk>>>(W, b, T);

    launch_pdl(heavy_edge_kernel, EDGE_GRID, blk,
               (const int4*)src, (const int4*)dst,
               (const float4*)r, (const float4*)rhat,
               (const float4*)z, T);

    launch_pdl(node0_kernel, NODE_GRID, blk,
               (const float4*)z, (const float4*)T, A, q1, (float4*)out);

    launch_pdl(light_edge_kernel, EDGE_GRID, blk,
               (const int4*)src, (const int4*)dst, (const float*)A, q1);

    launch_pdl(node_update1_kernel, NODE_GRID, blk,
               (const float4*)z, (const float4*)T, (const float*)q1, A, q2);

    launch_pdl(light_edge_kernel, EDGE_GRID, blk,
               (const int4*)src, (const int4*)dst, (const float*)A, q2);

    launch_pdl(node_update2_final_kernel, NODE_GRID, blk,
               (const float4*)z, (const float4*)T, (const float*)q2,
               (const float*)A, (float4*)out);
}